// round 5
// baseline (speedup 1.0000x reference)
#include <cuda_runtime.h>
#include <math.h>

#define THREADS 512
#define TB 128
#define PX 68           // pitch (floats) for X/H smem rows

// smem layout (floats):
//   buf0:  128*68 = 8704
//   buf1:  128*68 = 8704
//   extra: 1924   (4 GRU bias pairs + head smalls)
//   sB:    37808  (conv stage scratch+weights; reused as heads C1)
#define SMEM_FLOATS (8704 + 8704 + 1924 + 37808)
#define SMEM_BYTES  (SMEM_FLOATS * 4)

struct KParams {
    const float* in[32];
    float* out;
    int B;
};

// NaN-safe fast sigmoid/tanh (errors ~1e-6, well inside 1e-3 budget)
__device__ __forceinline__ float fsig(float x)  { return __fdividef(1.f, 1.f + __expf(-x)); }
__device__ __forceinline__ float ftanh(float x) { return 1.f - __fdividef(2.f, __expf(2.f * x) + 1.f); }

__device__ __forceinline__ void load_h(float* __restrict__ sH, const float* __restrict__ gmem,
                                       int gs0, int off, int tid)
{
    for (int idx = tid; idx < TB * 64; idx += THREADS) {
        int s = idx >> 6, j = idx & 63;
        sH[s * PX + j] = gmem[(size_t)(gs0 + s) * 256 + off + j];
    }
}

// GRU cell, j-split: thread (ts, tj) computes gates for samples {sb+ts+8u} at column tj.
// Weights read directly from global (L2/L1 cached); biases pre-staged in smem.
__device__ __forceinline__ void gru_cell(
    const float* __restrict__ sX, float* __restrict__ sH,
    const float* __restrict__ bias,                       // [384]: bi(192) | bh(192)
    const float* __restrict__ g_wih, const float* __restrict__ g_whh,
    float* __restrict__ out_mem, int gs0, int cell_off, int tid)
{
    const int ts = tid & 7;          // sample lane 0..7
    const int tj = tid >> 3;         // output column 0..63

    const float* wi0 = g_wih + (size_t)(tj      ) * 64;
    const float* wi1 = g_wih + (size_t)(tj + 64 ) * 64;
    const float* wi2 = g_wih + (size_t)(tj + 128) * 64;
    const float* wh0 = g_whh + (size_t)(tj      ) * 64;
    const float* wh1 = g_whh + (size_t)(tj + 64 ) * 64;
    const float* wh2 = g_whh + (size_t)(tj + 128) * 64;

    const float bi_r = bias[tj],       bh_r = bias[192 + tj];
    const float bi_z = bias[64 + tj],  bh_z = bias[256 + tj];
    const float bi_n = bias[128 + tj], bh_n = bias[320 + tj];

    for (int sub = 0; sub < 4; ++sub) {
        const int sb = sub * 32;
        float acc[4][6];
        #pragma unroll
        for (int u = 0; u < 4; u++)
            #pragma unroll
            for (int g = 0; g < 6; g++) acc[u][g] = 0.f;

        #pragma unroll 2
        for (int k = 0; k < 64; k += 4) {
            float4 xv[4], hv[4];
            #pragma unroll
            for (int u = 0; u < 4; u++) {
                int s = sb + ts + 8 * u;
                xv[u] = *reinterpret_cast<const float4*>(&sX[s * PX + k]);
                hv[u] = *reinterpret_cast<const float4*>(&sH[s * PX + k]);
            }
            const float4 a0 = __ldg(reinterpret_cast<const float4*>(wi0 + k));
            const float4 a1 = __ldg(reinterpret_cast<const float4*>(wi1 + k));
            const float4 a2 = __ldg(reinterpret_cast<const float4*>(wi2 + k));
            const float4 b0 = __ldg(reinterpret_cast<const float4*>(wh0 + k));
            const float4 b1 = __ldg(reinterpret_cast<const float4*>(wh1 + k));
            const float4 b2 = __ldg(reinterpret_cast<const float4*>(wh2 + k));
            #pragma unroll
            for (int u = 0; u < 4; u++) {
                acc[u][0] += xv[u].x * a0.x + xv[u].y * a0.y + xv[u].z * a0.z + xv[u].w * a0.w;
                acc[u][1] += xv[u].x * a1.x + xv[u].y * a1.y + xv[u].z * a1.z + xv[u].w * a1.w;
                acc[u][2] += xv[u].x * a2.x + xv[u].y * a2.y + xv[u].z * a2.z + xv[u].w * a2.w;
                acc[u][3] += hv[u].x * b0.x + hv[u].y * b0.y + hv[u].z * b0.z + hv[u].w * b0.w;
                acc[u][4] += hv[u].x * b1.x + hv[u].y * b1.y + hv[u].z * b1.z + hv[u].w * b1.w;
                acc[u][5] += hv[u].x * b2.x + hv[u].y * b2.y + hv[u].z * b2.z + hv[u].w * b2.w;
            }
        }
        __syncthreads();   // all k-loop reads of this subtile's sH rows complete
        #pragma unroll
        for (int u = 0; u < 4; u++) {
            int s  = sb + ts + 8 * u;
            int gs = gs0 + s;
            float r = fsig(acc[u][0] + acc[u][3] + bi_r + bh_r);
            float z = fsig(acc[u][1] + acc[u][4] + bi_z + bh_z);
            float n = ftanh(acc[u][2] + bi_n + r * (acc[u][5] + bh_n));
            float h = sH[s * PX + tj];
            float hn = (1.f - z) * n + z * h;
            sH[s * PX + tj] = hn;
            out_mem[(size_t)gs * 256 + cell_off + tj] = hn;
        }
        // no barrier needed: next subtile touches disjoint rows
    }
    __syncthreads();       // cell complete before buffers are reused
}

__global__ __launch_bounds__(THREADS, 1)
void fused_gru_ac_kernel(KParams P)
{
    extern __shared__ float sm[];
    float* buf0  = sm;
    float* buf1  = sm + 8704;
    float* extra = sm + 17408;           // 1924 floats
    float* sB    = sm + 19332;           // 37808 floats

    const int tid = threadIdx.x;
    const int gs0 = blockIdx.x * TB;
    const int Btot = P.B;

    const float* g_obs = P.in[0];
    const float* g_mem = P.in[1];
    float* out_mem = P.out + (size_t)4 * Btot;   // memory_out region

    // ---- stage conv weights + GRU biases + head smalls (one barrier) ----
    {
        const float* g;
        g = P.in[2]; for (int i = tid; i < 192;  i += THREADS) sB[i]         = g[i];  // conv w1
        g = P.in[3]; for (int i = tid; i < 16;   i += THREADS) sB[192 + i]   = g[i];  // conv b1
        g = P.in[4]; for (int i = tid; i < 2048; i += THREADS) sB[208 + i]   = g[i];  // conv w2
        g = P.in[5]; for (int i = tid; i < 32;   i += THREADS) sB[2256 + i]  = g[i];  // conv b2
        g = P.in[6]; for (int i = tid; i < 8192; i += THREADS) sB[2288 + i]  = g[i];  // conv w3
        g = P.in[7]; for (int i = tid; i < 64;   i += THREADS) sB[10480 + i] = g[i];  // conv b3
        // GRU biases: cell c -> extra[c*384 .. c*384+383] = bih | bhh
        const int bih_idx[4] = {10, 14, 18, 22};
        #pragma unroll
        for (int c = 0; c < 4; c++) {
            const float* gi = P.in[bih_idx[c]];
            const float* gh = P.in[bih_idx[c] + 1];
            for (int i = tid; i < 192; i += THREADS) {
                extra[c * 384 + i]       = gi[i];
                extra[c * 384 + 192 + i] = gh[i];
            }
        }
        g = P.in[26]; for (int i = tid; i < 192; i += THREADS) extra[1536 + i] = g[i]; // aw2
        g = P.in[27]; for (int i = tid; i < 3;   i += THREADS) extra[1728 + i] = g[i]; // ab2
        g = P.in[30]; for (int i = tid; i < 64;  i += THREADS) extra[1731 + i] = g[i]; // cw2
        g = P.in[31]; if (tid == 0) extra[1795] = g[0];                                // cb2
        g = P.in[25]; for (int i = tid; i < 64;  i += THREADS) extra[1796 + i] = g[i]; // ab1
        g = P.in[29]; for (int i = tid; i < 64;  i += THREADS) extra[1860 + i] = g[i]; // cb1
    }
    float* obsS = sB + 10544;   // 64*149
    float* Pm   = sB + 20080;   // 64*145
    float* o2   = sB + 29360;   // 64*132

    // ---------------- conv stack: 2 passes of 64 samples, 8 threads/sample ----------------
    for (int pass = 0; pass < 2; ++pass) {
        int sg0 = gs0 + pass * 64;
        __syncthreads();   // pass 0: staging done; pass 1: prev conv reads done
        for (int idx = tid; idx < 64 * 147; idx += THREADS) {
            int s = idx / 147, e = idx - s * 147;
            obsS[s * 149 + e] = g_obs[(size_t)(sg0 + s) * 147 + e];
        }
        __syncthreads();

        int s = tid >> 3, q = tid & 7;   // 8 threads per sample

        // conv1 (3->16, 2x2) + relu + maxpool2 -> Pm[16][3][3]   (2 out ch / thread)
        {
            float w1r[24], b1r[2];
            #pragma unroll
            for (int oc = 0; oc < 2; oc++) {
                int o = q * 2 + oc;
                #pragma unroll
                for (int m = 0; m < 12; m++) w1r[oc * 12 + m] = sB[o * 12 + m];
                b1r[oc] = sB[192 + o];
            }
            for (int i = 0; i < 3; i++)
                for (int j = 0; j < 3; j++) {
                    float xv[27];
                    #pragma unroll
                    for (int c = 0; c < 3; c++)
                        #pragma unroll
                        for (int a = 0; a < 3; a++)
                            #pragma unroll
                            for (int b = 0; b < 3; b++)
                                xv[c * 9 + a * 3 + b] =
                                    obsS[s * 149 + (2 * i + a) * 21 + (2 * j + b) * 3 + c];
                    #pragma unroll
                    for (int oc = 0; oc < 2; oc++) {
                        float mx = -1e30f;
                        #pragma unroll
                        for (int pi = 0; pi < 2; pi++)
                            #pragma unroll
                            for (int pj = 0; pj < 2; pj++) {
                                float a0 = b1r[oc];
                                #pragma unroll
                                for (int c = 0; c < 3; c++)
                                    #pragma unroll
                                    for (int ki = 0; ki < 2; ki++)
                                        #pragma unroll
                                        for (int kj = 0; kj < 2; kj++)
                                            a0 += xv[c * 9 + (pi + ki) * 3 + (pj + kj)] *
                                                  w1r[oc * 12 + c * 4 + ki * 2 + kj];
                                a0 = fmaxf(a0, 0.f);
                                mx = fmaxf(mx, a0);
                            }
                        Pm[s * 145 + (q * 2 + oc) * 9 + i * 3 + j] = mx;
                    }
                }
        }
        __syncthreads();

        // conv2 (16->32, 2x2 on 3x3) + relu -> o2[32][2][2]   (4 out ch / thread)
        #pragma unroll
        for (int pi = 0; pi < 2; pi++)
            #pragma unroll
            for (int pj = 0; pj < 2; pj++) {
                float xp[64];
                #pragma unroll
                for (int c = 0; c < 16; c++)
                    #pragma unroll
                    for (int a = 0; a < 2; a++)
                        #pragma unroll
                        for (int b = 0; b < 2; b++)
                            xp[c * 4 + a * 2 + b] = Pm[s * 145 + c * 9 + (pi + a) * 3 + (pj + b)];
                for (int o4 = 0; o4 < 4; o4++) {
                    int o = q * 4 + o4;
                    float a0 = sB[2256 + o];
                    #pragma unroll
                    for (int kk = 0; kk < 16; kk++) {
                        float4 w = *reinterpret_cast<const float4*>(&sB[208 + o * 64 + kk * 4]);
                        a0 += xp[kk * 4] * w.x + xp[kk * 4 + 1] * w.y +
                              xp[kk * 4 + 2] * w.z + xp[kk * 4 + 3] * w.w;
                    }
                    o2[s * 132 + o * 4 + pi * 2 + pj] = fmaxf(a0, 0.f);
                }
            }
        __syncthreads();

        // conv3 (32->64, 2x2 on 2x2) + relu -> x[64] into buf0   (8 out ch / thread)
        for (int o8 = 0; o8 < 8; o8++) {
            int o = q * 8 + o8;
            float a0 = sB[10480 + o];
            #pragma unroll
            for (int kk = 0; kk < 32; kk++) {
                float4 w  = *reinterpret_cast<const float4*>(&sB[2288 + o * 128 + kk * 4]);
                float4 x4 = *reinterpret_cast<const float4*>(&o2[s * 132 + kk * 4]);
                a0 += x4.x * w.x + x4.y * w.y + x4.z * w.z + x4.w * w.w;
            }
            buf0[(pass * 64 + s) * PX + o] = fmaxf(a0, 0.f);
        }
    }
    __syncthreads();

    // ---------------- 4 GRU cells ----------------
    float* Xp = buf0;
    float* Hp = buf1;

    load_h(Hp, g_mem, gs0, 0, tid);
    __syncthreads();
    gru_cell(Xp, Hp, extra + 0 * 384, P.in[8],  P.in[9],  out_mem, gs0, 0,   tid);
    { float* t = Xp; Xp = Hp; Hp = t; }

    load_h(Hp, g_mem, gs0, 64, tid);
    __syncthreads();
    gru_cell(Xp, Hp, extra + 1 * 384, P.in[12], P.in[13], out_mem, gs0, 64,  tid);
    { float* t = Xp; Xp = Hp; Hp = t; }

    load_h(Hp, g_mem, gs0, 128, tid);
    __syncthreads();
    gru_cell(Xp, Hp, extra + 2 * 384, P.in[16], P.in[17], out_mem, gs0, 128, tid);
    { float* t = Xp; Xp = Hp; Hp = t; }

    load_h(Hp, g_mem, gs0, 192, tid);
    __syncthreads();
    gru_cell(Xp, Hp, extra + 3 * 384, P.in[20], P.in[21], out_mem, gs0, 192, tid);
    { float* t = Xp; Xp = Hp; Hp = t; }
    // Xp = embedding [TB][PX], Hp = scratch (a1), sB free (C1)

    float* C1 = sB;   // 128 x PX

    // pass1: a1 = relu(emb @ actor_w1^T + b), c1 = relu(emb @ critic_w1^T + b)
    {
        const int ts = tid & 7, tj = tid >> 3;   // tj 0..63
        const float* wa = P.in[24] + (size_t)tj * 64;   // actor_w1 row tj
        const float* wc = P.in[28] + (size_t)tj * 64;   // critic_w1 row tj
        const float ba = extra[1796 + tj], bc = extra[1860 + tj];
        for (int sub = 0; sub < 4; ++sub) {
            int sb = sub * 32;
            float acc[4][2];
            #pragma unroll
            for (int u = 0; u < 4; u++) { acc[u][0] = 0.f; acc[u][1] = 0.f; }

            #pragma unroll 4
            for (int k = 0; k < 64; k += 4) {
                float4 xv[4];
                #pragma unroll
                for (int u = 0; u < 4; u++)
                    xv[u] = *reinterpret_cast<const float4*>(&Xp[(sb + ts + 8 * u) * PX + k]);
                float4 va = __ldg(reinterpret_cast<const float4*>(wa + k));
                float4 vc = __ldg(reinterpret_cast<const float4*>(wc + k));
                #pragma unroll
                for (int u = 0; u < 4; u++) {
                    acc[u][0] += xv[u].x * va.x + xv[u].y * va.y + xv[u].z * va.z + xv[u].w * va.w;
                    acc[u][1] += xv[u].x * vc.x + xv[u].y * vc.y + xv[u].z * vc.z + xv[u].w * vc.w;
                }
            }
            #pragma unroll
            for (int u = 0; u < 4; u++) {
                int s = sb + ts + 8 * u;
                Hp[s * PX + tj] = fmaxf(acc[u][0] + ba, 0.f);
                C1[s * PX + tj] = fmaxf(acc[u][1] + bc, 0.f);
            }
        }
    }
    __syncthreads();

    // final: logits + log_softmax (even threads of first 256), value (odd)
    if (tid < 256) {
        int s2 = tid >> 1;
        int gs = gs0 + s2;
        if ((tid & 1) == 0) {
            float l0 = extra[1728], l1 = extra[1729], l2 = extra[1730];
            #pragma unroll 8
            for (int k = 0; k < 64; k++) {
                float a = Hp[s2 * PX + k];
                l0 += a * extra[1536 + k];
                l1 += a * extra[1600 + k];
                l2 += a * extra[1664 + k];
            }
            float mx = fmaxf(l0, fmaxf(l1, l2));
            float lse = mx + __logf(__expf(l0 - mx) + __expf(l1 - mx) + __expf(l2 - mx));
            P.out[(size_t)gs * 3 + 0] = l0 - lse;
            P.out[(size_t)gs * 3 + 1] = l1 - lse;
            P.out[(size_t)gs * 3 + 2] = l2 - lse;
        } else {
            float v = extra[1795];
            #pragma unroll 8
            for (int k = 0; k < 64; k++) v += C1[s2 * PX + k] * extra[1731 + k];
            P.out[(size_t)3 * Btot + gs] = v;
        }
    }
}

extern "C" void kernel_launch(void* const* d_in, const int* in_sizes, int n_in,
                              void* d_out, int out_size)
{
    KParams P;
    for (int i = 0; i < 32; i++) P.in[i] = (const float*)d_in[i];
    P.out = (float*)d_out;
    P.B = in_sizes[1] / 256;   // memory is [B, 256]

    cudaFuncSetAttribute(fused_gru_ac_kernel,
                         cudaFuncAttributeMaxDynamicSharedMemorySize, SMEM_BYTES);

    int grid = P.B / TB;
    fused_gru_ac_kernel<<<grid, THREADS, SMEM_BYTES>>>(P);
}